// round 7
// baseline (speedup 1.0000x reference)
#include <cuda_runtime.h>
#include <math.h>

// Problem constants
#define BATCH 4
#define NOBJ  256
#define HDIM  512
#define CD1   256      // collision detector hidden 1
#define CD2   128      // collision detector hidden 2

// Output layout (float32, concatenated in reference return order)
#define OFF_MASS 0
#define OFF_FRIC 1024
#define OFF_ELAS 2048
#define OFF_DENS 3072
#define OFF_VEL  4096
#define OFF_FRC  7168
#define OFF_COL  10240

// Scratch: A = x @ cd_w1[:512] + b1   (bias folded), B = x @ cd_w1[512:]
__device__ float g_A[BATCH * NOBJ * CD1];   // 1 MB
__device__ float g_B[BATCH * NOBJ * CD1];   // 1 MB

// ---------------------------------------------------------------------------
// Kernel 1: per-row heads. 8 rows per block, 256 threads.
//  - pp hidden (relu(x@pp_w1+b1)) -> only 4 columns of pp_w2 needed
//  - A/B halves of collision layer 1
//  - velocity / force heads
// ---------------------------------------------------------------------------
__global__ void __launch_bounds__(256) heads_kernel(
    const float* __restrict__ x,
    const float* __restrict__ pp_w1, const float* __restrict__ pp_b1,
    const float* __restrict__ pp_w2, const float* __restrict__ pp_b2,
    const float* __restrict__ cd_w1, const float* __restrict__ cd_b1,
    const float* __restrict__ vel_w, const float* __restrict__ vel_b,
    const float* __restrict__ frc_w, const float* __restrict__ frc_b,
    float* __restrict__ out)
{
    __shared__ float sx[8][HDIM];    // 16 KB
    __shared__ float sh1[8][HDIM];   // 16 KB (pp hidden)

    const int tid  = threadIdx.x;
    const int row0 = blockIdx.x * 8;      // flattened (b*256 + n)

    // load 8 rows of x
    for (int idx = tid; idx < 8 * HDIM; idx += 256) {
        sx[idx >> 9][idx & 511] = x[row0 * HDIM + idx];
    }
    __syncthreads();

    // ---- physics-predictor hidden: thread handles columns tid and tid+256
    {
        float a0[8], a1[8];
        #pragma unroll
        for (int r = 0; r < 8; r++) { a0[r] = 0.f; a1[r] = 0.f; }
        #pragma unroll 4
        for (int k = 0; k < HDIM; k++) {
            float w0 = pp_w1[k * 512 + tid];
            float w1 = pp_w1[k * 512 + tid + 256];
            #pragma unroll
            for (int r = 0; r < 8; r++) {
                float xv = sx[r][k];
                a0[r] = fmaf(xv, w0, a0[r]);
                a1[r] = fmaf(xv, w1, a1[r]);
            }
        }
        float b0  = pp_b1[tid];
        float b1v = pp_b1[tid + 256];
        #pragma unroll
        for (int r = 0; r < 8; r++) {
            sh1[r][tid]       = fmaxf(a0[r] + b0,  0.f);
            sh1[r][tid + 256] = fmaxf(a1[r] + b1v, 0.f);
        }
    }

    // ---- A / B halves of collision layer-1 (bias folded into A)
    {
        float aA[8], aB[8];
        #pragma unroll
        for (int r = 0; r < 8; r++) { aA[r] = 0.f; aB[r] = 0.f; }
        #pragma unroll 4
        for (int k = 0; k < HDIM; k++) {
            float wA = cd_w1[k * CD1 + tid];
            float wB = cd_w1[(k + 512) * CD1 + tid];
            #pragma unroll
            for (int r = 0; r < 8; r++) {
                float xv = sx[r][k];
                aA[r] = fmaf(xv, wA, aA[r]);
                aB[r] = fmaf(xv, wB, aB[r]);
            }
        }
        float bb = cd_b1[tid];
        #pragma unroll
        for (int r = 0; r < 8; r++) {
            g_A[(row0 + r) * CD1 + tid] = aA[r] + bb;
            g_B[(row0 + r) * CD1 + tid] = aB[r];
        }
    }
    __syncthreads();   // sh1 fully written before cross-column warp dots

    // ---- small heads via warp dots: warp r handles row row0+r, tasks q=0..9
    const int warp = tid >> 5;
    const int lane = tid & 31;
    const int r    = warp;
    const int row  = row0 + r;

    for (int q = 0; q < 10; q++) {
        float sum = 0.f;
        if (q < 4) {                           // p[:,q] = sh1 @ pp_w2[:,q]
            for (int k = lane; k < HDIM; k += 32)
                sum = fmaf(sh1[r][k], pp_w2[k * 128 + q], sum);
        } else if (q < 7) {                    // velocities
            int c = q - 4;
            for (int k = lane; k < HDIM; k += 32)
                sum = fmaf(sx[r][k], vel_w[k * 3 + c], sum);
        } else {                               // forces
            int c = q - 7;
            for (int k = lane; k < HDIM; k += 32)
                sum = fmaf(sx[r][k], frc_w[k * 3 + c], sum);
        }
        #pragma unroll
        for (int o = 16; o > 0; o >>= 1)
            sum += __shfl_xor_sync(0xffffffffu, sum, o);
        if (lane == 0) {
            if (q < 4) {
                float s = 1.f / (1.f + expf(-(sum + pp_b2[q])));
                if      (q == 0) out[OFF_MASS + row] = s * 100.f;
                else if (q == 1) out[OFF_FRIC + row] = s;
                else if (q == 2) out[OFF_ELAS + row] = s;
                else             out[OFF_DENS + row] = s * 10.f;
            } else if (q < 7) {
                out[OFF_VEL + row * 3 + (q - 4)] = sum + vel_b[q - 4];
            } else {
                out[OFF_FRC + row * 3 + (q - 7)] = sum + frc_b[q - 7];
            }
        }
    }
}

// ---------------------------------------------------------------------------
// Kernel 2: pairwise collisions. One block per 8x8 row-block tile of the
// upper triangle (incl. diagonal tiles), per batch. 2112 blocks, 256 thr.
// h1 = relu(A[i] + B[j]); h2 = relu(h1 @ W2 + b2); s = h2 . w3 + b3.
// Register-tiled GEMM: thread = 8 pairs x 4 cols; K chunked by 32 in SMEM.
// ---------------------------------------------------------------------------
__global__ void __launch_bounds__(256) pair_kernel(
    const float* __restrict__ cd_w2, const float* __restrict__ cd_b2,
    const float* __restrict__ cd_w3, const float* __restrict__ cd_b3,
    float* __restrict__ out)
{
    __shared__ float sA[8][260];                      // padded: avoid bank conflicts
    __shared__ float sB[8][260];
    __shared__ __align__(16) float sh1[32][64];       // [k-chunk][pair]
    __shared__ __align__(16) float sW2[32][128];      // [k-chunk][col]
    __shared__ float sW3[CD2];
    __shared__ float sB2[CD2];

    const int tid = threadIdx.x;

    // decode (batch, upper-tri tile) from blockIdx
    int b = blockIdx.x / 528;
    int t = blockIdx.x % 528;
    int bi = 0, rem = t;
    while (rem >= 32 - bi) { rem -= 32 - bi; bi++; }
    int bj = bi + rem;
    const int i0 = bi * 8, j0 = bj * 8;
    const int rowbase = b * NOBJ;

    // stage A rows (i-side, bias folded) and B rows (j-side)
    for (int idx = tid; idx < 8 * 256; idx += 256) {
        int rr = idx >> 8, k = idx & 255;
        sA[rr][k] = g_A[(rowbase + i0 + rr) * CD1 + k];
        sB[rr][k] = g_B[(rowbase + j0 + rr) * CD1 + k];
    }
    if (tid < CD2) { sW3[tid] = cd_w3[tid]; sB2[tid] = cd_b2[tid]; }
    __syncthreads();

    const int warp = tid >> 5;        // = ti  (pairs p0..p0+7 share i)
    const int lane = tid & 31;
    const int p0   = warp * 8;
    const int c0   = lane * 4;

    float acc[8][4];
    #pragma unroll
    for (int pi = 0; pi < 8; pi++)
        #pragma unroll
        for (int ci = 0; ci < 4; ci++) acc[pi][ci] = 0.f;

    for (int kc = 0; kc < 8; kc++) {
        const int k0 = kc * 32;
        // build h1 chunk: sh1[kk][p] = relu(A[ti][k0+kk] + B[tj][k0+kk])
        #pragma unroll
        for (int v = 0; v < 8; v++) {
            int idx = v * 256 + tid;
            int kk = idx >> 6;
            int p  = idx & 63;
            sh1[kk][p] = fmaxf(sA[p >> 3][k0 + kk] + sB[p & 7][k0 + kk], 0.f);
        }
        // stage W2 chunk (rows k0..k0+31, contiguous 16 KB)
        {
            const float4* src = (const float4*)(cd_w2 + k0 * CD2);
            float4* dst = (float4*)sW2;
            #pragma unroll
            for (int v = 0; v < 4; v++) dst[v * 256 + tid] = src[v * 256 + tid];
        }
        __syncthreads();

        #pragma unroll
        for (int kk = 0; kk < 32; kk++) {
            float4 ha = *(const float4*)&sh1[kk][p0];
            float4 hb = *(const float4*)&sh1[kk][p0 + 4];
            float4 w  = *(const float4*)&sW2[kk][c0];
            float hv[8] = {ha.x, ha.y, ha.z, ha.w, hb.x, hb.y, hb.z, hb.w};
            float wv[4] = {w.x, w.y, w.z, w.w};
            #pragma unroll
            for (int pi = 0; pi < 8; pi++)
                #pragma unroll
                for (int ci = 0; ci < 4; ci++)
                    acc[pi][ci] = fmaf(hv[pi], wv[ci], acc[pi][ci]);
        }
        __syncthreads();
    }

    // epilogue: bias + relu + dot with w3, reduce across the warp's 32 col-threads
    float partial[8];
    #pragma unroll
    for (int pi = 0; pi < 8; pi++) {
        float s = 0.f;
        #pragma unroll
        for (int ci = 0; ci < 4; ci++) {
            float h2 = fmaxf(acc[pi][ci] + sB2[c0 + ci], 0.f);
            s = fmaf(h2, sW3[c0 + ci], s);
        }
        partial[pi] = s;
    }
    float myS = 0.f;
    #pragma unroll
    for (int pi = 0; pi < 8; pi++) {
        float v = partial[pi];
        #pragma unroll
        for (int o = 16; o > 0; o >>= 1)
            v += __shfl_xor_sync(0xffffffffu, v, o);
        if (lane == pi) myS = v;
    }
    if (lane < 8) {
        int i = i0 + warp;
        int j = j0 + lane;
        float* cm = out + OFF_COL + b * (NOBJ * NOBJ);
        if (i < j) {
            float prob = 1.f / (1.f + expf(-(myS + cd_b3[0])));
            cm[i * NOBJ + j] = prob;
            cm[j * NOBJ + i] = prob;
        } else if (i == j) {
            cm[i * NOBJ + i] = 0.f;   // d_out is poisoned; diagonal must be 0
        }
    }
}

// ---------------------------------------------------------------------------
extern "C" void kernel_launch(void* const* d_in, const int* in_sizes, int n_in,
                              void* d_out, int out_size)
{
    (void)in_sizes; (void)n_in; (void)out_size;
    const float* x     = (const float*)d_in[0];
    const float* pp_w1 = (const float*)d_in[1];
    const float* pp_b1 = (const float*)d_in[2];
    const float* pp_w2 = (const float*)d_in[3];
    const float* pp_b2 = (const float*)d_in[4];
    const float* cd_w1 = (const float*)d_in[5];
    const float* cd_b1 = (const float*)d_in[6];
    const float* cd_w2 = (const float*)d_in[7];
    const float* cd_b2 = (const float*)d_in[8];
    const float* cd_w3 = (const float*)d_in[9];
    const float* cd_b3 = (const float*)d_in[10];
    const float* vel_w = (const float*)d_in[11];
    const float* vel_b = (const float*)d_in[12];
    const float* frc_w = (const float*)d_in[13];
    const float* frc_b = (const float*)d_in[14];
    float* out = (float*)d_out;

    heads_kernel<<<128, 256>>>(x, pp_w1, pp_b1, pp_w2, pp_b2,
                               cd_w1, cd_b1, vel_w, vel_b, frc_w, frc_b, out);
    pair_kernel<<<4 * 528, 256>>>(cd_w2, cd_b2, cd_w3, cd_b3, out);
}

// round 9
// speedup vs baseline: 2.4870x; 2.4870x over previous
#include <cuda_runtime.h>
#include <math.h>
#include <stdint.h>

// ---------------------------------------------------------------------------
// Problem constants
#define BATCH 4
#define NOBJ  256
#define HDIM  512
#define CD1   256      // collision hidden 1 (= K of pair GEMM)
#define CD2   128      // collision hidden 2 (= N of pair GEMM)

// Output layout (float32, reference return order)
#define OFF_MASS 0
#define OFF_FRIC 1024
#define OFF_ELAS 2048
#define OFF_DENS 3072
#define OFF_VEL  4096
#define OFF_FRC  7168
#define OFF_COL  10240

// Scratch (device globals; no allocation allowed)
__device__ float    g_H [BATCH * NOBJ * HDIM];   // relu(x@pp_w1+b1)   2 MB
__device__ float    g_AB[BATCH * NOBJ * HDIM];   // [A | B] halves     2 MB
__device__ uint32_t g_W2t[CD2 * CD1];            // cd_w2 transposed, tf32 bits

// ---------------------------------------------------------------------------
static __device__ __forceinline__ uint32_t f32_tf32(float v) {
    uint32_t r;
    asm("cvt.rna.tf32.f32 %0, %1;" : "=r"(r) : "f"(v));
    return r;
}

// m16n8k8 tf32 warp MMA, D = A*B + D (fp32 accum)
static __device__ __forceinline__ void mma_tf32(
    float c[4], const uint32_t a[4], const uint32_t b[2])
{
    asm volatile(
        "mma.sync.aligned.m16n8k8.row.col.f32.tf32.tf32.f32 "
        "{%0,%1,%2,%3}, {%4,%5,%6,%7}, {%8,%9}, {%0,%1,%2,%3};\n"
        : "+f"(c[0]), "+f"(c[1]), "+f"(c[2]), "+f"(c[3])
        : "r"(a[0]), "r"(a[1]), "r"(a[2]), "r"(a[3]),
          "r"(b[0]), "r"(b[1]));
}

// ---------------------------------------------------------------------------
// Kernel 0: transpose + tf32-quantize cd_w2 [256][128] -> g_W2t [n][k]
// ---------------------------------------------------------------------------
__global__ void __launch_bounds__(256) prep_w2t(const float* __restrict__ cd_w2)
{
    int idx = blockIdx.x * 256 + threadIdx.x;     // grid 32 -> 8192 threads
    #pragma unroll
    for (int v = 0; v < 4; v++) {
        int e = idx + v * 8192;                   // 0 .. 32767
        int k = e >> 7, n = e & 127;
        g_W2t[n * CD1 + k] = f32_tf32(cd_w2[k * CD2 + n]);
    }
}

// ---------------------------------------------------------------------------
// Kernel 1: heads GEMM via tf32 mma.sync. CTA tile 128(M) x 128(N), K=512.
// grid (4 nblk, 8 mblk, 2): z=0 -> g_H = relu(x@pp_w1 + pp_b1)
//                           z=1 -> g_AB = x@[cd_w1a | cd_w1b] (+cd_b1 on A half)
// ---------------------------------------------------------------------------
__global__ void __launch_bounds__(256, 2) heads_gemm(
    const float* __restrict__ x,
    const float* __restrict__ pp_w1, const float* __restrict__ pp_b1,
    const float* __restrict__ cd_w1, const float* __restrict__ cd_b1)
{
    __shared__ float    sbias[128];
    __shared__ uint32_t xa[128 * 36];    // A chunk [r][kk], pad 36 (conflict-free)
    __shared__ uint32_t wb[32 * 136];    // B chunk [kk][n], pad 136 (conflict-free)

    const int tid = threadIdx.x;
    const int wid = tid >> 5, lane = tid & 31;
    const int g = lane >> 2, t4 = lane & 3;
    const int wm = wid & 1, wn = wid >> 1;     // warp grid 2(m) x 4(n)

    const int n0 = blockIdx.x * 128;
    const int m0 = blockIdx.y * 128;
    const int z  = blockIdx.z;

    const float* Wbase;
    int wstride, ncol0;
    if (z == 0) { Wbase = pp_w1; wstride = 512; ncol0 = n0; }
    else        { Wbase = cd_w1 + (n0 >= 256 ? 512 * 256 : 0); wstride = 256; ncol0 = n0 & 255; }

    if (tid < 128) {
        float bv;
        if (z == 0) bv = pp_b1[n0 + tid];
        else        bv = (n0 + tid < 256) ? cd_b1[n0 + tid] : 0.f;
        sbias[tid] = bv;
    }

    float acc[4][4][4];
    #pragma unroll
    for (int mt = 0; mt < 4; mt++)
        #pragma unroll
        for (int nt = 0; nt < 4; nt++)
            #pragma unroll
            for (int r = 0; r < 4; r++) acc[mt][nt][r] = 0.f;

    for (int c = 0; c < 16; c++) {
        const int k0 = c * 32;
        __syncthreads();
        // stage x chunk (tf32), coalesced 128B rows
        #pragma unroll
        for (int v = 0; v < 16; v++) {
            int idx = v * 256 + tid;
            int r = idx >> 5, kk = idx & 31;
            xa[r * 36 + kk] = f32_tf32(x[(m0 + r) * HDIM + k0 + kk]);
        }
        // stage W chunk (tf32), [kk][n], coalesced reads, conflict-free sts
        #pragma unroll
        for (int v = 0; v < 16; v++) {
            int idx = v * 256 + tid;
            int kk = idx >> 7, n = idx & 127;
            wb[kk * 136 + n] = f32_tf32(Wbase[(k0 + kk) * wstride + ncol0 + n]);
        }
        __syncthreads();

        #pragma unroll
        for (int ks = 0; ks < 4; ks++) {
            const int kb = ks * 8;
            uint32_t a[4][4], bf[4][2];
            #pragma unroll
            for (int mt = 0; mt < 4; mt++) {
                int base = (wm * 64 + mt * 16 + g) * 36 + kb + t4;
                a[mt][0] = xa[base];
                a[mt][1] = xa[base + 8 * 36];
                a[mt][2] = xa[base + 4];
                a[mt][3] = xa[base + 8 * 36 + 4];
            }
            #pragma unroll
            for (int nt = 0; nt < 4; nt++) {
                int nb = wn * 32 + nt * 8 + g;
                bf[nt][0] = wb[(kb + t4) * 136 + nb];
                bf[nt][1] = wb[(kb + t4 + 4) * 136 + nb];
            }
            #pragma unroll
            for (int mt = 0; mt < 4; mt++)
                #pragma unroll
                for (int nt = 0; nt < 4; nt++)
                    mma_tf32(acc[mt][nt], a[mt], bf[nt]);
        }
    }

    // epilogue: bias (+relu for z=0), write float2
    float* outp = (z == 0) ? g_H : g_AB;
    const bool dorelu = (z == 0);
    #pragma unroll
    for (int mt = 0; mt < 4; mt++) {
        int row = m0 + wm * 64 + mt * 16 + g;
        #pragma unroll
        for (int nt = 0; nt < 4; nt++) {
            int cl = wn * 32 + nt * 8 + 2 * t4;   // local col (even)
            float b0v = sbias[cl], b1v = sbias[cl + 1];
            float v0 = acc[mt][nt][0] + b0v;
            float v1 = acc[mt][nt][1] + b1v;
            float v2 = acc[mt][nt][2] + b0v;
            float v3 = acc[mt][nt][3] + b1v;
            if (dorelu) {
                v0 = fmaxf(v0, 0.f); v1 = fmaxf(v1, 0.f);
                v2 = fmaxf(v2, 0.f); v3 = fmaxf(v3, 0.f);
            }
            *(float2*)&outp[row * 512 + n0 + cl]       = make_float2(v0, v1);
            *(float2*)&outp[(row + 8) * 512 + n0 + cl] = make_float2(v2, v3);
        }
    }
}

// ---------------------------------------------------------------------------
// Kernel 2: small heads (mass/friction/elasticity/density, vel, frc).
// Warp per row; weights staged to smem column-major-by-q.
// ---------------------------------------------------------------------------
__global__ void __launch_bounds__(256) small_heads(
    const float* __restrict__ x,
    const float* __restrict__ pp_w2, const float* __restrict__ pp_b2,
    const float* __restrict__ vel_w, const float* __restrict__ vel_b,
    const float* __restrict__ frc_w, const float* __restrict__ frc_b,
    float* __restrict__ out)
{
    __shared__ float sw[HDIM * 10];   // 20 KB
    const int tid  = threadIdx.x;
    const int row0 = blockIdx.x * 8;

    for (int idx = tid; idx < HDIM * 10; idx += 256) {
        int k = idx / 10, q = idx - k * 10;
        float v;
        if      (q < 4) v = pp_w2[k * 128 + q];
        else if (q < 7) v = vel_w[k * 3 + (q - 4)];
        else            v = frc_w[k * 3 + (q - 7)];
        sw[idx] = v;
    }
    __syncthreads();

    const int warp = tid >> 5, lane = tid & 31;
    const int row  = row0 + warp;
    const float* srcH = g_H + row * HDIM;
    const float* srcX = x   + row * HDIM;

    for (int q = 0; q < 10; q++) {
        const float* src = (q < 4) ? srcH : srcX;
        float sum = 0.f;
        for (int k = lane; k < HDIM; k += 32)
            sum = fmaf(src[k], sw[k * 10 + q], sum);
        #pragma unroll
        for (int o = 16; o > 0; o >>= 1)
            sum += __shfl_xor_sync(0xffffffffu, sum, o);
        if (lane == 0) {
            if (q < 4) {
                float s = 1.f / (1.f + expf(-(sum + pp_b2[q])));
                if      (q == 0) out[OFF_MASS + row] = s * 100.f;
                else if (q == 1) out[OFF_FRIC + row] = s;
                else if (q == 2) out[OFF_ELAS + row] = s;
                else             out[OFF_DENS + row] = s * 10.f;
            } else if (q < 7) {
                out[OFF_VEL + row * 3 + (q - 4)] = sum + vel_b[q - 4];
            } else {
                out[OFF_FRC + row * 3 + (q - 7)] = sum + frc_b[q - 7];
            }
        }
    }
}

// ---------------------------------------------------------------------------
// Kernel 3: pairwise collisions via tf32 mma.sync.
// CTA: 128 pairs (16 i x 8 j) x 128 cols, K=256 in 8 chunks of 32.
// ---------------------------------------------------------------------------
__global__ void __launch_bounds__(256, 2) pair_kernel(
    const float* __restrict__ cd_b2, const float* __restrict__ cd_w3,
    const float* __restrict__ cd_b3, float* __restrict__ out)
{
    __shared__ float    b2s[CD2];
    __shared__ float    w3s[CD2];
    __shared__ float    sred[128 * 5];
    __shared__ uint32_t sh1[128 * 36];   // h1 chunk [p][kk], tf32, pad 36
    __shared__ uint32_t w2c[128 * 36];   // W2t chunk [n][kk], tf32, pad 36

    const int tid = threadIdx.x;
    const int wid = tid >> 5, lane = tid & 31;
    const int g = lane >> 2, t4 = lane & 3;
    const int wm = wid & 1, wn = wid >> 1;   // warp grid 2(m) x 4(n)

    // decode (batch, tile): bi = 16-row i-block (0..15), bj = 8-row j-block >= 2bi
    int b = blockIdx.x / 272;
    int t = blockIdx.x % 272;
    int bi = 0, rem = t;
    while (rem >= 32 - 2 * bi) { rem -= 32 - 2 * bi; bi++; }
    int bj = 2 * bi + rem;
    const int i0 = bi * 16, j0 = bj * 8;
    const int rowbase = b * NOBJ;

    if (tid < CD2) { b2s[tid] = cd_b2[tid]; w3s[tid] = cd_w3[tid]; }

    float acc[4][4][4];
    #pragma unroll
    for (int mt = 0; mt < 4; mt++)
        #pragma unroll
        for (int nt = 0; nt < 4; nt++)
            #pragma unroll
            for (int r = 0; r < 4; r++) acc[mt][nt][r] = 0.f;

    for (int c = 0; c < 8; c++) {
        const int k0 = c * 32;
        __syncthreads();
        // build h1 chunk: relu(A[i(p)] + B[j(p)]) -> tf32. Warp reads are
        // 128B-coalesced from g_AB; i-rows hit L1 on reuse across j.
        #pragma unroll
        for (int v = 0; v < 16; v++) {
            int idx = v * 256 + tid;
            int p = idx >> 5, kk = idx & 31;
            float av = g_AB[(rowbase + i0 + (p >> 3)) * 512 + k0 + kk];
            float bv = g_AB[(rowbase + j0 + (p & 7)) * 512 + 256 + k0 + kk];
            sh1[p * 36 + kk] = f32_tf32(fmaxf(av + bv, 0.f));
        }
        // copy pre-quantized W2t chunk (coalesced, conflict-free)
        #pragma unroll
        for (int v = 0; v < 16; v++) {
            int idx = v * 256 + tid;
            int n = idx >> 5, kk = idx & 31;
            w2c[n * 36 + kk] = g_W2t[n * CD1 + k0 + kk];
        }
        __syncthreads();

        #pragma unroll
        for (int ks = 0; ks < 4; ks++) {
            const int kb = ks * 8;
            uint32_t a[4][4], bf[4][2];
            #pragma unroll
            for (int mt = 0; mt < 4; mt++) {
                int base = (wm * 64 + mt * 16 + g) * 36 + kb + t4;
                a[mt][0] = sh1[base];
                a[mt][1] = sh1[base + 8 * 36];
                a[mt][2] = sh1[base + 4];
                a[mt][3] = sh1[base + 8 * 36 + 4];
            }
            #pragma unroll
            for (int nt = 0; nt < 4; nt++) {
                int base = (wn * 32 + nt * 8 + g) * 36 + kb + t4;
                bf[nt][0] = w2c[base];
                bf[nt][1] = w2c[base + 4];
            }
            #pragma unroll
            for (int mt = 0; mt < 4; mt++)
                #pragma unroll
                for (int nt = 0; nt < 4; nt++)
                    mma_tf32(acc[mt][nt], a[mt], bf[nt]);
        }
    }

    // epilogue: per-element bias+relu+*w3, reduce 4-lane groups, then warps
    #pragma unroll
    for (int mt = 0; mt < 4; mt++) {
        float s0 = 0.f, s1 = 0.f;    // rows g and g+8 of this m-tile
        #pragma unroll
        for (int nt = 0; nt < 4; nt++) {
            int cl = wn * 32 + nt * 8 + 2 * t4;
            float h;
            h = fmaxf(acc[mt][nt][0] + b2s[cl],     0.f); s0 = fmaf(h, w3s[cl],     s0);
            h = fmaxf(acc[mt][nt][1] + b2s[cl + 1], 0.f); s0 = fmaf(h, w3s[cl + 1], s0);
            h = fmaxf(acc[mt][nt][2] + b2s[cl],     0.f); s1 = fmaf(h, w3s[cl],     s1);
            h = fmaxf(acc[mt][nt][3] + b2s[cl + 1], 0.f); s1 = fmaf(h, w3s[cl + 1], s1);
        }
        s0 += __shfl_xor_sync(0xffffffffu, s0, 1);
        s0 += __shfl_xor_sync(0xffffffffu, s0, 2);
        s1 += __shfl_xor_sync(0xffffffffu, s1, 1);
        s1 += __shfl_xor_sync(0xffffffffu, s1, 2);
        if (t4 == 0) {
            int p = wm * 64 + mt * 16 + g;
            sred[p * 5 + wn]       = s0;
            sred[(p + 8) * 5 + wn] = s1;
        }
    }
    __syncthreads();

    if (tid < 128) {
        float sum = sred[tid * 5] + sred[tid * 5 + 1] +
                    sred[tid * 5 + 2] + sred[tid * 5 + 3] + cd_b3[0];
        int i = i0 + (tid >> 3);
        int j = j0 + (tid & 7);
        float* cm = out + OFF_COL + b * (NOBJ * NOBJ);
        if (i < j) {
            float prob = 1.f / (1.f + expf(-sum));
            cm[i * NOBJ + j] = prob;
            cm[j * NOBJ + i] = prob;
        } else if (i == j) {
            cm[i * NOBJ + i] = 0.f;   // d_out poisoned; diagonal must be 0
        }
    }
}

// ---------------------------------------------------------------------------
extern "C" void kernel_launch(void* const* d_in, const int* in_sizes, int n_in,
                              void* d_out, int out_size)
{
    (void)in_sizes; (void)n_in; (void)out_size;
    const float* x     = (const float*)d_in[0];
    const float* pp_w1 = (const float*)d_in[1];
    const float* pp_b1 = (const float*)d_in[2];
    const float* pp_w2 = (const float*)d_in[3];
    const float* pp_b2 = (const float*)d_in[4];
    const float* cd_w1 = (const float*)d_in[5];
    const float* cd_b1 = (const float*)d_in[6];
    const float* cd_w2 = (const float*)d_in[7];
    const float* cd_b2 = (const float*)d_in[8];
    const float* cd_w3 = (const float*)d_in[9];
    const float* cd_b3 = (const float*)d_in[10];
    const float* vel_w = (const float*)d_in[11];
    const float* vel_b = (const float*)d_in[12];
    const float* frc_w = (const float*)d_in[13];
    const float* frc_b = (const float*)d_in[14];
    float* out = (float*)d_out;

    prep_w2t<<<32, 256>>>(cd_w2);
    heads_gemm<<<dim3(4, 8, 2), 256>>>(x, pp_w1, pp_b1, cd_w1, cd_b1);
    small_heads<<<128, 256>>>(x, pp_w2, pp_b2, vel_w, vel_b, frc_w, frc_b, out);
    pair_kernel<<<4 * 272, 256>>>(cd_b2, cd_w3, cd_b3, out);
}

// round 11
// speedup vs baseline: 3.4277x; 1.3783x over previous
#include <cuda_runtime.h>
#include <math.h>
#include <stdint.h>

// ---------------------------------------------------------------------------
// Problem constants
#define BATCH 4
#define NOBJ  256
#define HDIM  512
#define CD1   256      // collision hidden 1 (= K of pair GEMM)
#define CD2   128      // collision hidden 2 (= N of pair GEMM)

// Output layout (float32, reference return order)
#define OFF_MASS 0
#define OFF_FRIC 1024
#define OFF_ELAS 2048
#define OFF_DENS 3072
#define OFF_VEL  4096
#define OFF_FRC  7168
#define OFF_COL  10240

// Scratch (device globals; no allocation allowed)
__device__ float    g_H [BATCH * NOBJ * HDIM];        // relu(x@pp_w1+b1)
__device__ float    g_AB[BATCH * NOBJ * HDIM];        // [A | B] halves
__device__ __align__(16) uint32_t g_W2pk[32 * 128 * 8]; // W2 tf32, fragment-packed

// ---------------------------------------------------------------------------
static __device__ __forceinline__ uint32_t f32_tf32(float v) {
    uint32_t r;
    asm("cvt.rna.tf32.f32 %0, %1;" : "=r"(r) : "f"(v));
    return r;
}

// m16n8k8 tf32 warp MMA, D = A*B + D (fp32 accum)
static __device__ __forceinline__ void mma_tf32(
    float c[4], const uint32_t a[4], const uint32_t b[2])
{
    asm volatile(
        "mma.sync.aligned.m16n8k8.row.col.f32.tf32.tf32.f32 "
        "{%0,%1,%2,%3}, {%4,%5,%6,%7}, {%8,%9}, {%0,%1,%2,%3};\n"
        : "+f"(c[0]), "+f"(c[1]), "+f"(c[2]), "+f"(c[3])
        : "r"(a[0]), "r"(a[1]), "r"(a[2]), "r"(a[3]),
          "r"(b[0]), "r"(b[1]));
}

static __device__ __forceinline__ void cp_async16(uint32_t dst_smem, const void* src) {
    asm volatile("cp.async.cg.shared.global [%0], [%1], 16;"
                 :: "r"(dst_smem), "l"(src) : "memory");
}

// ---------------------------------------------------------------------------
// Kernel 0: pack cd_w2 [256k][128n] -> g_W2pk, tf32, b-fragment order:
// e = ((ksg*128 + n)*4 + t4)*2 + h  holds cd_w2[(ksg*8 + t4 + 4h)*128 + n]
// Grid 128 x 256 = 32768 threads: one per element (R10 bug: grid 32 left
// 3/4 of the table zero -> K truncated to 64 in layer 2).
// ---------------------------------------------------------------------------
__global__ void __launch_bounds__(256) prep_w2t(const float* __restrict__ cd_w2)
{
    int e = blockIdx.x * 256 + threadIdx.x;           // 0 .. 32767
    int h = e & 1, t4 = (e >> 1) & 3, n = (e >> 3) & 127, ksg = e >> 10;
    g_W2pk[e] = f32_tf32(cd_w2[(ksg * 8 + t4 + 4 * h) * CD2 + n]);
}

// ---------------------------------------------------------------------------
// Kernel 1: heads GEMM via tf32 mma.sync. CTA tile 64(M) x 128(N), K=512.
// grid (4 nblk, 16 mblk, 2): z=0 -> g_H = relu(x@pp_w1 + pp_b1)
//                            z=1 -> g_AB = x@[cd_w1a | cd_w1b] (+cd_b1 on A half)
// ---------------------------------------------------------------------------
__global__ void __launch_bounds__(256, 2) heads_gemm(
    const float* __restrict__ x,
    const float* __restrict__ pp_w1, const float* __restrict__ pp_b1,
    const float* __restrict__ cd_w1, const float* __restrict__ cd_b1)
{
    __shared__ float    sbias[128];
    __shared__ uint32_t xa[64 * 36];     // A chunk [r][kk], pad 36
    __shared__ uint32_t wb[32 * 136];    // B chunk [kk][n], pad 136

    const int tid = threadIdx.x;
    const int wid = tid >> 5, lane = tid & 31;
    const int g = lane >> 2, t4 = lane & 3;
    const int wm = wid & 1, wn = wid >> 1;     // warp grid 2(m) x 4(n)

    const int n0 = blockIdx.x * 128;
    const int m0 = blockIdx.y * 64;
    const int z  = blockIdx.z;

    const float* Wbase;
    int wstride, ncol0;
    if (z == 0) { Wbase = pp_w1; wstride = 512; ncol0 = n0; }
    else        { Wbase = cd_w1 + (n0 >= 256 ? 512 * 256 : 0); wstride = 256; ncol0 = n0 & 255; }

    if (tid < 128) {
        float bv;
        if (z == 0) bv = pp_b1[n0 + tid];
        else        bv = (n0 + tid < 256) ? cd_b1[n0 + tid] : 0.f;
        sbias[tid] = bv;
    }

    float acc[2][4][4];
    #pragma unroll
    for (int mt = 0; mt < 2; mt++)
        #pragma unroll
        for (int nt = 0; nt < 4; nt++)
            #pragma unroll
            for (int r = 0; r < 4; r++) acc[mt][nt][r] = 0.f;

    for (int c = 0; c < 16; c++) {
        const int k0 = c * 32;
        __syncthreads();
        #pragma unroll
        for (int v = 0; v < 8; v++) {       // stage x chunk 64x32
            int idx = v * 256 + tid;
            int r = idx >> 5, kk = idx & 31;
            xa[r * 36 + kk] = f32_tf32(x[(m0 + r) * HDIM + k0 + kk]);
        }
        #pragma unroll
        for (int v = 0; v < 16; v++) {      // stage W chunk 32x128
            int idx = v * 256 + tid;
            int kk = idx >> 7, n = idx & 127;
            wb[kk * 136 + n] = f32_tf32(Wbase[(k0 + kk) * wstride + ncol0 + n]);
        }
        __syncthreads();

        #pragma unroll
        for (int ks = 0; ks < 4; ks++) {
            const int kb = ks * 8;
            uint32_t a[2][4], bf[4][2];
            #pragma unroll
            for (int mt = 0; mt < 2; mt++) {
                int base = (wm * 32 + mt * 16 + g) * 36 + kb + t4;
                a[mt][0] = xa[base];
                a[mt][1] = xa[base + 8 * 36];
                a[mt][2] = xa[base + 4];
                a[mt][3] = xa[base + 8 * 36 + 4];
            }
            #pragma unroll
            for (int nt = 0; nt < 4; nt++) {
                int nb = wn * 32 + nt * 8 + g;
                bf[nt][0] = wb[(kb + t4) * 136 + nb];
                bf[nt][1] = wb[(kb + t4 + 4) * 136 + nb];
            }
            #pragma unroll
            for (int mt = 0; mt < 2; mt++)
                #pragma unroll
                for (int nt = 0; nt < 4; nt++)
                    mma_tf32(acc[mt][nt], a[mt], bf[nt]);
        }
    }

    float* outp = (z == 0) ? g_H : g_AB;
    const bool dorelu = (z == 0);
    #pragma unroll
    for (int mt = 0; mt < 2; mt++) {
        int row = m0 + wm * 32 + mt * 16 + g;
        #pragma unroll
        for (int nt = 0; nt < 4; nt++) {
            int cl = wn * 32 + nt * 8 + 2 * t4;
            float b0v = sbias[cl], b1v = sbias[cl + 1];
            float v0 = acc[mt][nt][0] + b0v;
            float v1 = acc[mt][nt][1] + b1v;
            float v2 = acc[mt][nt][2] + b0v;
            float v3 = acc[mt][nt][3] + b1v;
            if (dorelu) {
                v0 = fmaxf(v0, 0.f); v1 = fmaxf(v1, 0.f);
                v2 = fmaxf(v2, 0.f); v3 = fmaxf(v3, 0.f);
            }
            *(float2*)&outp[row * 512 + n0 + cl]       = make_float2(v0, v1);
            *(float2*)&outp[(row + 8) * 512 + n0 + cl] = make_float2(v2, v3);
        }
    }
}

// ---------------------------------------------------------------------------
// Kernel 2: small heads (mass/friction/elasticity/density, vel, frc).
// ---------------------------------------------------------------------------
__global__ void __launch_bounds__(256) small_heads(
    const float* __restrict__ x,
    const float* __restrict__ pp_w2, const float* __restrict__ pp_b2,
    const float* __restrict__ vel_w, const float* __restrict__ vel_b,
    const float* __restrict__ frc_w, const float* __restrict__ frc_b,
    float* __restrict__ out)
{
    __shared__ float sw[HDIM * 10];
    const int tid  = threadIdx.x;
    const int row0 = blockIdx.x * 8;

    for (int idx = tid; idx < HDIM * 10; idx += 256) {
        int k = idx / 10, q = idx - k * 10;
        float v;
        if      (q < 4) v = pp_w2[k * 128 + q];
        else if (q < 7) v = vel_w[k * 3 + (q - 4)];
        else            v = frc_w[k * 3 + (q - 7)];
        sw[idx] = v;
    }
    __syncthreads();

    const int warp = tid >> 5, lane = tid & 31;
    const int row  = row0 + warp;
    const float* srcH = g_H + row * HDIM;
    const float* srcX = x   + row * HDIM;

    for (int q = 0; q < 10; q++) {
        const float* src = (q < 4) ? srcH : srcX;
        float sum = 0.f;
        for (int k = lane; k < HDIM; k += 32)
            sum = fmaf(src[k], sw[k * 10 + q], sum);
        #pragma unroll
        for (int o = 16; o > 0; o >>= 1)
            sum += __shfl_xor_sync(0xffffffffu, sum, o);
        if (lane == 0) {
            if (q < 4) {
                float s = 1.f / (1.f + expf(-(sum + pp_b2[q])));
                if      (q == 0) out[OFF_MASS + row] = s * 100.f;
                else if (q == 1) out[OFF_FRIC + row] = s;
                else if (q == 2) out[OFF_ELAS + row] = s;
                else             out[OFF_DENS + row] = s * 10.f;
            } else if (q < 7) {
                out[OFF_VEL + row * 3 + (q - 4)] = sum + vel_b[q - 4];
            } else {
                out[OFF_FRC + row * 3 + (q - 7)] = sum + frc_b[q - 7];
            }
        }
    }
}

// ---------------------------------------------------------------------------
// Kernel 3: pairwise collisions. CTA: 128 pairs (16i x 8j) x 128 cols, K=256
// in 4 chunks of 64. Fragment-packed h1 (STS.128/LDS.128) and W2 (LDS.64),
// cp.async for W2 chunks, A/B rows staged in smem.
// Dynamic smem layout (bytes):
//   0      h1   32768  (2048 quads x 16B: [mb8][ks8][g8][t4_4]{4 regs})
//   32768  w2   32768  (packed chunk)
//   65536  sA   16*260*4 = 16640
//   82176  sB   8*260*4  = 8320
//   90496  b2s  512
//   91008  w3s  512
//   91520  sred 2560
//   total  94080
// ---------------------------------------------------------------------------
#define PAIR_SMEM 94080

__global__ void __launch_bounds__(256, 2) pair_kernel(
    const float* __restrict__ cd_b2, const float* __restrict__ cd_w3,
    const float* __restrict__ cd_b3, float* __restrict__ out)
{
    extern __shared__ char sm[];
    uint32_t* h1  = (uint32_t*)sm;
    uint32_t* w2  = (uint32_t*)(sm + 32768);
    float*    sA  = (float*)(sm + 65536);
    float*    sB  = (float*)(sm + 82176);
    float*    b2s = (float*)(sm + 90496);
    float*    w3s = (float*)(sm + 91008);
    float*    sred= (float*)(sm + 91520);

    const int tid = threadIdx.x;
    const int wid = tid >> 5, lane = tid & 31;
    const int g = lane >> 2, t4 = lane & 3;
    const int wm = wid & 1, wn = wid >> 1;   // warp grid 2(m) x 4(n)

    // decode (batch, tile): bi = 16-row i-block, bj = 8-row j-block >= 2bi
    int b = blockIdx.x / 272;
    int t = blockIdx.x % 272;
    int bi = 0, rem = t;
    while (rem >= 32 - 2 * bi) { rem -= 32 - 2 * bi; bi++; }
    int bj = 2 * bi + rem;
    const int i0 = bi * 16, j0 = bj * 8;
    const int rowbase = b * NOBJ;

    if (tid < CD2) { b2s[tid] = cd_b2[tid]; w3s[tid] = cd_w3[tid]; }

    // stage A rows (16x256) and B rows (8x256), padded stride 260
    #pragma unroll
    for (int v = 0; v < 16; v++) {
        int idx = v * 256 + tid;
        int r = idx >> 8, kk = idx & 255;
        sA[r * 260 + kk] = g_AB[(rowbase + i0 + r) * 512 + kk];
    }
    #pragma unroll
    for (int v = 0; v < 8; v++) {
        int idx = v * 256 + tid;
        int r = idx >> 8, kk = idx & 255;
        sB[r * 260 + kk] = g_AB[(rowbase + j0 + r) * 512 + 256 + kk];
    }

    float acc[4][4][4];
    #pragma unroll
    for (int mt = 0; mt < 4; mt++)
        #pragma unroll
        for (int nt = 0; nt < 4; nt++)
            #pragma unroll
            for (int r = 0; r < 4; r++) acc[mt][nt][r] = 0.f;

    const uint32_t w2_smem_base = (uint32_t)__cvta_generic_to_shared(w2);
    __syncthreads();

    for (int c = 0; c < 4; c++) {
        if (c) __syncthreads();            // prev MMA done before overwrite
        const int k0 = c * 64;

        // cp.async the packed W2 chunk (32 KB), overlapped with h1 build
        {
            const uint32_t* src = g_W2pk + c * 8192;
            #pragma unroll
            for (int v = 0; v < 8; v++) {
                int off = v * 1024 + tid * 4;         // u32 offset, 16B steps
                cp_async16(w2_smem_base + off * 4, src + off);
            }
        }

        // build h1 chunk as fragment quads; STS.128, conflict-free
        #pragma unroll
        for (int v = 0; v < 8; v++) {
            int q = v * 256 + tid;
            int qt4 = q & 3, qg = (q >> 2) & 7, ksl = (q >> 5) & 7, mb = q >> 8;
            int kc = k0 + ksl * 8 + qt4;
            float a0  = sA[(2 * mb) * 260 + kc];
            float a0b = sA[(2 * mb) * 260 + kc + 4];
            float a1  = sA[(2 * mb + 1) * 260 + kc];
            float a1b = sA[(2 * mb + 1) * 260 + kc + 4];
            float bb0 = sB[qg * 260 + kc];
            float bb1 = sB[qg * 260 + kc + 4];
            uint4 qv;
            qv.x = f32_tf32(fmaxf(a0  + bb0, 0.f));   // (row g,   k t4)
            qv.y = f32_tf32(fmaxf(a1  + bb0, 0.f));   // (row g+8, k t4)
            qv.z = f32_tf32(fmaxf(a0b + bb1, 0.f));   // (row g,   k t4+4)
            qv.w = f32_tf32(fmaxf(a1b + bb1, 0.f));   // (row g+8, k t4+4)
            *(uint4*)(h1 + q * 4) = qv;
        }
        asm volatile("cp.async.wait_all;" ::: "memory");
        __syncthreads();

        // MMA: 8 k-steps of 8
        #pragma unroll
        for (int ksl = 0; ksl < 8; ksl++) {
            uint32_t a[4][4], bf[4][2];
            #pragma unroll
            for (int mt = 0; mt < 4; mt++) {
                int mbf = wm * 4 + mt;
                uint4 av = *(const uint4*)(h1 + (((mbf * 8 + ksl) * 8 + g) * 4 + t4) * 4);
                a[mt][0] = av.x; a[mt][1] = av.y; a[mt][2] = av.z; a[mt][3] = av.w;
            }
            #pragma unroll
            for (int nt = 0; nt < 4; nt++) {
                int n = wn * 32 + nt * 8 + g;
                uint2 bv = *(const uint2*)(w2 + ((ksl * 128 + n) * 4 + t4) * 2);
                bf[nt][0] = bv.x; bf[nt][1] = bv.y;
            }
            #pragma unroll
            for (int mt = 0; mt < 4; mt++)
                #pragma unroll
                for (int nt = 0; nt < 4; nt++)
                    mma_tf32(acc[mt][nt], a[mt], bf[nt]);
        }
    }

    // epilogue: bias+relu+*w3, 4-lane shfl reduce, cross-warp smem reduce
    #pragma unroll
    for (int mt = 0; mt < 4; mt++) {
        float s0 = 0.f, s1 = 0.f;
        #pragma unroll
        for (int nt = 0; nt < 4; nt++) {
            int cl = wn * 32 + nt * 8 + 2 * t4;
            float h;
            h = fmaxf(acc[mt][nt][0] + b2s[cl],     0.f); s0 = fmaf(h, w3s[cl],     s0);
            h = fmaxf(acc[mt][nt][1] + b2s[cl + 1], 0.f); s0 = fmaf(h, w3s[cl + 1], s0);
            h = fmaxf(acc[mt][nt][2] + b2s[cl],     0.f); s1 = fmaf(h, w3s[cl],     s1);
            h = fmaxf(acc[mt][nt][3] + b2s[cl + 1], 0.f); s1 = fmaf(h, w3s[cl + 1], s1);
        }
        s0 += __shfl_xor_sync(0xffffffffu, s0, 1);
        s0 += __shfl_xor_sync(0xffffffffu, s0, 2);
        s1 += __shfl_xor_sync(0xffffffffu, s1, 1);
        s1 += __shfl_xor_sync(0xffffffffu, s1, 2);
        if (t4 == 0) {
            int p = wm * 64 + mt * 16 + g;
            sred[p * 5 + wn]       = s0;
            sred[(p + 8) * 5 + wn] = s1;
        }
    }
    __syncthreads();

    if (tid < 128) {
        float sum = sred[tid * 5] + sred[tid * 5 + 1] +
                    sred[tid * 5 + 2] + sred[tid * 5 + 3] + cd_b3[0];
        int i = i0 + (tid >> 3);
        int j = j0 + (tid & 7);
        float* cm = out + OFF_COL + b * (NOBJ * NOBJ);
        if (i < j) {
            float prob = 1.f / (1.f + expf(-sum));
            cm[i * NOBJ + j] = prob;
            cm[j * NOBJ + i] = prob;
        } else if (i == j) {
            cm[i * NOBJ + i] = 0.f;   // d_out poisoned; diagonal must be 0
        }
    }
}

// ---------------------------------------------------------------------------
extern "C" void kernel_launch(void* const* d_in, const int* in_sizes, int n_in,
                              void* d_out, int out_size)
{
    (void)in_sizes; (void)n_in; (void)out_size;
    const float* x     = (const float*)d_in[0];
    const float* pp_w1 = (const float*)d_in[1];
    const float* pp_b1 = (const float*)d_in[2];
    const float* pp_w2 = (const float*)d_in[3];
    const float* pp_b2 = (const float*)d_in[4];
    const float* cd_w1 = (const float*)d_in[5];
    const float* cd_b1 = (const float*)d_in[6];
    const float* cd_w2 = (const float*)d_in[7];
    const float* cd_b2 = (const float*)d_in[8];
    const float* cd_w3 = (const float*)d_in[9];
    const float* cd_b3 = (const float*)d_in[10];
    const float* vel_w = (const float*)d_in[11];
    const float* vel_b = (const float*)d_in[12];
    const float* frc_w = (const float*)d_in[13];
    const float* frc_b = (const float*)d_in[14];
    float* out = (float*)d_out;

    cudaFuncSetAttribute(pair_kernel, cudaFuncAttributeMaxDynamicSharedMemorySize, PAIR_SMEM);

    prep_w2t<<<128, 256>>>(cd_w2);                 // FIX: full 32768-element pack
    heads_gemm<<<dim3(4, 16, 2), 256>>>(x, pp_w1, pp_b1, cd_w1, cd_b1);
    small_heads<<<128, 256>>>(x, pp_w2, pp_b2, vel_w, vel_b, frc_w, frc_b, out);
    pair_kernel<<<4 * 272, 256, PAIR_SMEM>>>(cd_b2, cd_w3, cd_b3, out);
}

// round 12
// speedup vs baseline: 4.8807x; 1.4239x over previous
#include <cuda_runtime.h>
#include <cuda_fp16.h>
#include <math.h>
#include <stdint.h>

// ---------------------------------------------------------------------------
// Problem constants
#define BATCH 4
#define NOBJ  256
#define HDIM  512
#define CD1   256      // collision hidden 1 (= K of pair GEMM)
#define CD2   128      // collision hidden 2 (= N of pair GEMM)

// Output layout (float32, reference return order)
#define OFF_MASS 0
#define OFF_FRIC 1024
#define OFF_ELAS 2048
#define OFF_DENS 3072
#define OFF_VEL  4096
#define OFF_FRC  7168
#define OFF_COL  10240

// Scratch (device globals; no allocation allowed)
__device__ float g_H [BATCH * NOBJ * HDIM];          // relu(x@pp_w1+b1)
__device__ float g_AB[BATCH * NOBJ * HDIM];          // [A | B] halves
// W2 as fp16, b-fragment packed: entry e=((kslg*128+n)*4+t4), uint2 =
// { half2(W2[k][n],W2[k+1][n]), half2(W2[k+8][n],W2[k+9][n]) }, k=kslg*16+2*t4
__device__ __align__(16) uint2 g_W2pkh[16 * 128 * 4];  // 64 KB

// ---------------------------------------------------------------------------
static __device__ __forceinline__ uint32_t f32_tf32(float v) {
    uint32_t r;
    asm("cvt.rna.tf32.f32 %0, %1;" : "=r"(r) : "f"(v));
    return r;
}

// m16n8k8 tf32 warp MMA (heads GEMM)
static __device__ __forceinline__ void mma_tf32(
    float c[4], const uint32_t a[4], const uint32_t b[2])
{
    asm volatile(
        "mma.sync.aligned.m16n8k8.row.col.f32.tf32.tf32.f32 "
        "{%0,%1,%2,%3}, {%4,%5,%6,%7}, {%8,%9}, {%0,%1,%2,%3};\n"
        : "+f"(c[0]), "+f"(c[1]), "+f"(c[2]), "+f"(c[3])
        : "r"(a[0]), "r"(a[1]), "r"(a[2]), "r"(a[3]),
          "r"(b[0]), "r"(b[1]));
}

// m16n8k16 fp16 warp MMA, fp32 accum (pair GEMM)
static __device__ __forceinline__ void mma_f16(
    float c[4], const uint32_t a[4], const uint32_t b[2])
{
    asm volatile(
        "mma.sync.aligned.m16n8k16.row.col.f32.f16.f16.f32 "
        "{%0,%1,%2,%3}, {%4,%5,%6,%7}, {%8,%9}, {%0,%1,%2,%3};\n"
        : "+f"(c[0]), "+f"(c[1]), "+f"(c[2]), "+f"(c[3])
        : "r"(a[0]), "r"(a[1]), "r"(a[2]), "r"(a[3]),
          "r"(b[0]), "r"(b[1]));
}

static __device__ __forceinline__ void cp_async16(uint32_t dst_smem, const void* src) {
    asm volatile("cp.async.cg.shared.global [%0], [%1], 16;"
                 :: "r"(dst_smem), "l"(src) : "memory");
}

static __device__ __forceinline__ uint32_t pack_h2(float lo, float hi) {
    __half2 h = __floats2half2_rn(lo, hi);
    return *(uint32_t*)&h;
}

// ---------------------------------------------------------------------------
// Kernel 0: pack cd_w2 [256k][128n] -> g_W2pkh (fp16 b-fragment order).
// 8192 entries, grid 32 x 256 = 8192 exactly.
// ---------------------------------------------------------------------------
__global__ void __launch_bounds__(256) prep_w2t(const float* __restrict__ cd_w2)
{
    int e = blockIdx.x * 256 + threadIdx.x;     // 0 .. 8191
    int t4 = e & 3, n = (e >> 2) & 127, kslg = e >> 9;
    int k = kslg * 16 + 2 * t4;
    uint2 v;
    v.x = pack_h2(cd_w2[k * CD2 + n],       cd_w2[(k + 1) * CD2 + n]);
    v.y = pack_h2(cd_w2[(k + 8) * CD2 + n], cd_w2[(k + 9) * CD2 + n]);
    g_W2pkh[e] = v;
}

// ---------------------------------------------------------------------------
// Kernel 1: heads GEMM via tf32 mma.sync. CTA tile 64(M) x 128(N), K=512.
// grid (4 nblk, 16 mblk, 2): z=0 -> g_H = relu(x@pp_w1 + pp_b1)
//                            z=1 -> g_AB = x@[cd_w1a | cd_w1b] (+cd_b1 on A half)
// ---------------------------------------------------------------------------
__global__ void __launch_bounds__(256, 2) heads_gemm(
    const float* __restrict__ x,
    const float* __restrict__ pp_w1, const float* __restrict__ pp_b1,
    const float* __restrict__ cd_w1, const float* __restrict__ cd_b1)
{
    __shared__ float    sbias[128];
    __shared__ uint32_t xa[64 * 36];     // A chunk [r][kk], pad 36
    __shared__ uint32_t wb[32 * 136];    // B chunk [kk][n], pad 136

    const int tid = threadIdx.x;
    const int wid = tid >> 5, lane = tid & 31;
    const int g = lane >> 2, t4 = lane & 3;
    const int wm = wid & 1, wn = wid >> 1;     // warp grid 2(m) x 4(n)

    const int n0 = blockIdx.x * 128;
    const int m0 = blockIdx.y * 64;
    const int z  = blockIdx.z;

    const float* Wbase;
    int wstride, ncol0;
    if (z == 0) { Wbase = pp_w1; wstride = 512; ncol0 = n0; }
    else        { Wbase = cd_w1 + (n0 >= 256 ? 512 * 256 : 0); wstride = 256; ncol0 = n0 & 255; }

    if (tid < 128) {
        float bv;
        if (z == 0) bv = pp_b1[n0 + tid];
        else        bv = (n0 + tid < 256) ? cd_b1[n0 + tid] : 0.f;
        sbias[tid] = bv;
    }

    float acc[2][4][4];
    #pragma unroll
    for (int mt = 0; mt < 2; mt++)
        #pragma unroll
        for (int nt = 0; nt < 4; nt++)
            #pragma unroll
            for (int r = 0; r < 4; r++) acc[mt][nt][r] = 0.f;

    for (int c = 0; c < 16; c++) {
        const int k0 = c * 32;
        __syncthreads();
        #pragma unroll
        for (int v = 0; v < 8; v++) {       // stage x chunk 64x32
            int idx = v * 256 + tid;
            int r = idx >> 5, kk = idx & 31;
            xa[r * 36 + kk] = f32_tf32(x[(m0 + r) * HDIM + k0 + kk]);
        }
        #pragma unroll
        for (int v = 0; v < 16; v++) {      // stage W chunk 32x128
            int idx = v * 256 + tid;
            int kk = idx >> 7, n = idx & 127;
            wb[kk * 136 + n] = f32_tf32(Wbase[(k0 + kk) * wstride + ncol0 + n]);
        }
        __syncthreads();

        #pragma unroll
        for (int ks = 0; ks < 4; ks++) {
            const int kb = ks * 8;
            uint32_t a[2][4], bf[4][2];
            #pragma unroll
            for (int mt = 0; mt < 2; mt++) {
                int base = (wm * 32 + mt * 16 + g) * 36 + kb + t4;
                a[mt][0] = xa[base];
                a[mt][1] = xa[base + 8 * 36];
                a[mt][2] = xa[base + 4];
                a[mt][3] = xa[base + 8 * 36 + 4];
            }
            #pragma unroll
            for (int nt = 0; nt < 4; nt++) {
                int nb = wn * 32 + nt * 8 + g;
                bf[nt][0] = wb[(kb + t4) * 136 + nb];
                bf[nt][1] = wb[(kb + t4 + 4) * 136 + nb];
            }
            #pragma unroll
            for (int mt = 0; mt < 2; mt++)
                #pragma unroll
                for (int nt = 0; nt < 4; nt++)
                    mma_tf32(acc[mt][nt], a[mt], bf[nt]);
        }
    }

    float* outp = (z == 0) ? g_H : g_AB;
    const bool dorelu = (z == 0);
    #pragma unroll
    for (int mt = 0; mt < 2; mt++) {
        int row = m0 + wm * 32 + mt * 16 + g;
        #pragma unroll
        for (int nt = 0; nt < 4; nt++) {
            int cl = wn * 32 + nt * 8 + 2 * t4;
            float b0v = sbias[cl], b1v = sbias[cl + 1];
            float v0 = acc[mt][nt][0] + b0v;
            float v1 = acc[mt][nt][1] + b1v;
            float v2 = acc[mt][nt][2] + b0v;
            float v3 = acc[mt][nt][3] + b1v;
            if (dorelu) {
                v0 = fmaxf(v0, 0.f); v1 = fmaxf(v1, 0.f);
                v2 = fmaxf(v2, 0.f); v3 = fmaxf(v3, 0.f);
            }
            *(float2*)&outp[row * 512 + n0 + cl]       = make_float2(v0, v1);
            *(float2*)&outp[(row + 8) * 512 + n0 + cl] = make_float2(v2, v3);
        }
    }
}

// ---------------------------------------------------------------------------
// Kernel 2: small heads (mass/friction/elasticity/density, vel, frc).
// ---------------------------------------------------------------------------
__global__ void __launch_bounds__(256) small_heads(
    const float* __restrict__ x,
    const float* __restrict__ pp_w2, const float* __restrict__ pp_b2,
    const float* __restrict__ vel_w, const float* __restrict__ vel_b,
    const float* __restrict__ frc_w, const float* __restrict__ frc_b,
    float* __restrict__ out)
{
    __shared__ float sw[HDIM * 10];
    const int tid  = threadIdx.x;
    const int row0 = blockIdx.x * 8;

    for (int idx = tid; idx < HDIM * 10; idx += 256) {
        int k = idx / 10, q = idx - k * 10;
        float v;
        if      (q < 4) v = pp_w2[k * 128 + q];
        else if (q < 7) v = vel_w[k * 3 + (q - 4)];
        else            v = frc_w[k * 3 + (q - 7)];
        sw[idx] = v;
    }
    __syncthreads();

    const int warp = tid >> 5, lane = tid & 31;
    const int row  = row0 + warp;
    const float* srcH = g_H + row * HDIM;
    const float* srcX = x   + row * HDIM;

    for (int q = 0; q < 10; q++) {
        const float* src = (q < 4) ? srcH : srcX;
        float sum = 0.f;
        for (int k = lane; k < HDIM; k += 32)
            sum = fmaf(src[k], sw[k * 10 + q], sum);
        #pragma unroll
        for (int o = 16; o > 0; o >>= 1)
            sum += __shfl_xor_sync(0xffffffffu, sum, o);
        if (lane == 0) {
            if (q < 4) {
                float s = 1.f / (1.f + expf(-(sum + pp_b2[q])));
                if      (q == 0) out[OFF_MASS + row] = s * 100.f;
                else if (q == 1) out[OFF_FRIC + row] = s;
                else if (q == 2) out[OFF_ELAS + row] = s;
                else             out[OFF_DENS + row] = s * 10.f;
            } else if (q < 7) {
                out[OFF_VEL + row * 3 + (q - 4)] = sum + vel_b[q - 4];
            } else {
                out[OFF_FRC + row * 3 + (q - 7)] = sum + frc_b[q - 7];
            }
        }
    }
}

// ---------------------------------------------------------------------------
// Kernel 3: pairwise collisions via fp16 m16n8k16.
// CTA: 128 pairs (16i x 8j) x 128 cols, K=256 in 4 chunks of 64.
// h1 and W2 double-buffered (1 sync per chunk). fp32 A+B add, single
// fp32->fp16 rounding after relu (precision-equivalent to tf32 path).
// Dynamic smem layout (bytes):
//   0      h1    2 x 16384   (1024 quads x 16B: [mb8][ksl4][g8][t4_4])
//   32768  w2    2 x 16384   (b-frag packed chunk)
//   65536  sA    16*264*4 = 16896   (stride 264 = 8 mod 32 words)
//   82432  sB    8*264*4  = 8448
//   90880  b2s   512
//   91392  w3s   512
//   91904  sred  2560
//   total  94464  (2 CTAs/SM = 189 KB)
// ---------------------------------------------------------------------------
#define PAIR_SMEM 94464

__global__ void __launch_bounds__(256, 2) pair_kernel(
    const float* __restrict__ cd_b2, const float* __restrict__ cd_w3,
    const float* __restrict__ cd_b3, float* __restrict__ out)
{
    extern __shared__ char sm[];
    float* sA  = (float*)(sm + 65536);
    float* sB  = (float*)(sm + 82432);
    float* b2s = (float*)(sm + 90880);
    float* w3s = (float*)(sm + 91392);
    float* sred= (float*)(sm + 91904);

    const int tid = threadIdx.x;
    const int wid = tid >> 5, lane = tid & 31;
    const int g = lane >> 2, t4 = lane & 3;
    const int wm = wid & 1, wn = wid >> 1;   // warp grid 2(m) x 4(n)

    // decode (batch, tile): bi = 16-row i-block, bj = 8-row j-block >= 2bi
    int b = blockIdx.x / 272;
    int t = blockIdx.x % 272;
    int bi = 0, rem = t;
    while (rem >= 32 - 2 * bi) { rem -= 32 - 2 * bi; bi++; }
    int bj = 2 * bi + rem;
    const int i0 = bi * 16, j0 = bj * 8;
    const int rowbase = b * NOBJ;

    if (tid < CD2) { b2s[tid] = cd_b2[tid]; w3s[tid] = cd_w3[tid]; }

    // stage A rows (16x256) and B rows (8x256), fp32, stride 264
    #pragma unroll
    for (int v = 0; v < 16; v++) {
        int idx = v * 256 + tid;
        int r = idx >> 8, kk = idx & 255;
        sA[r * 264 + kk] = g_AB[(rowbase + i0 + r) * 512 + kk];
    }
    #pragma unroll
    for (int v = 0; v < 8; v++) {
        int idx = v * 256 + tid;
        int r = idx >> 8, kk = idx & 255;
        sB[r * 264 + kk] = g_AB[(rowbase + j0 + r) * 512 + 256 + kk];
    }

    float acc[4][4][4];
    #pragma unroll
    for (int mt = 0; mt < 4; mt++)
        #pragma unroll
        for (int nt = 0; nt < 4; nt++)
            #pragma unroll
            for (int r = 0; r < 4; r++) acc[mt][nt][r] = 0.f;

    const uint32_t w2_smem = (uint32_t)__cvta_generic_to_shared(sm + 32768);
    __syncthreads();

    for (int c = 0; c < 4; c++) {
        const int buf = c & 1;
        const int k0 = c * 64;

        // cp.async the packed W2 chunk (16 KB) into wbuf, overlapped w/ build
        {
            const uint4* src = (const uint4*)(g_W2pkh + c * 2048);
            uint32_t dst = w2_smem + buf * 16384;
            #pragma unroll
            for (int v = 0; v < 4; v++) {
                int e = v * 256 + tid;
                cp_async16(dst + e * 16, src + e);
            }
        }

        // build h1 chunk as fp16 fragment quads (fp32 add, one rounding)
        {
            uint4* hq = (uint4*)(sm + buf * 16384);
            #pragma unroll
            for (int v = 0; v < 4; v++) {
                int q = v * 256 + tid;
                int t4q = q & 3, gq = (q >> 2) & 7, kslq = (q >> 5) & 3, mbq = q >> 7;
                int kb = k0 + kslq * 16 + 2 * t4q;
                const float* Ar0 = sA + (2 * mbq) * 264 + kb;
                const float* Ar1 = Ar0 + 264;
                const float* Br  = sB + gq * 264 + kb;
                float2 a0l = *(const float2*)Ar0;
                float2 a0h = *(const float2*)(Ar0 + 8);
                float2 a1l = *(const float2*)Ar1;
                float2 a1h = *(const float2*)(Ar1 + 8);
                float2 bl  = *(const float2*)Br;
                float2 bh  = *(const float2*)(Br + 8);
                uint4 qv;
                qv.x = pack_h2(fmaxf(a0l.x + bl.x, 0.f), fmaxf(a0l.y + bl.y, 0.f));
                qv.y = pack_h2(fmaxf(a1l.x + bl.x, 0.f), fmaxf(a1l.y + bl.y, 0.f));
                qv.z = pack_h2(fmaxf(a0h.x + bh.x, 0.f), fmaxf(a0h.y + bh.y, 0.f));
                qv.w = pack_h2(fmaxf(a1h.x + bh.x, 0.f), fmaxf(a1h.y + bh.y, 0.f));
                hq[q] = qv;
            }
        }
        asm volatile("cp.async.wait_all;" ::: "memory");
        __syncthreads();

        // MMA: 4 k-steps of 16
        const uint4* hbase = (const uint4*)(sm + buf * 16384);
        const uint2* wbase = (const uint2*)(sm + 32768 + buf * 16384);
        #pragma unroll
        for (int ksl = 0; ksl < 4; ksl++) {
            uint32_t a[4][4], bf[4][2];
            #pragma unroll
            for (int mt = 0; mt < 4; mt++) {
                int mbf = wm * 4 + mt;
                uint4 av = hbase[((mbf * 4 + ksl) * 8 + g) * 4 + t4];
                a[mt][0] = av.x; a[mt][1] = av.y; a[mt][2] = av.z; a[mt][3] = av.w;
            }
            #pragma unroll
            for (int nt = 0; nt < 4; nt++) {
                int n = wn * 32 + nt * 8 + g;
                uint2 bv = wbase[(ksl * 128 + n) * 4 + t4];
                bf[nt][0] = bv.x; bf[nt][1] = bv.y;
            }
            #pragma unroll
            for (int mt = 0; mt < 4; mt++)
                #pragma unroll
                for (int nt = 0; nt < 4; nt++)
                    mma_f16(acc[mt][nt], a[mt], bf[nt]);
        }
    }

    // epilogue: bias+relu+*w3, 4-lane shfl reduce, cross-warp smem reduce
    #pragma unroll
    for (int mt = 0; mt < 4; mt++) {
        float s0 = 0.f, s1 = 0.f;
        #pragma unroll
        for (int nt = 0; nt < 4; nt++) {
            int cl = wn * 32 + nt * 8 + 2 * t4;
            float h;
            h = fmaxf(acc[mt][nt][0] + b2s[cl],     0.f); s0 = fmaf(h, w3s[cl],     s0);
            h = fmaxf(acc[mt][nt][1] + b2s[cl + 1], 0.f); s0 = fmaf(h, w3s[cl + 1], s0);
            h = fmaxf(acc[mt][nt][2] + b2s[cl],     0.f); s1 = fmaf(h, w3s[cl],     s1);
            h = fmaxf(acc[mt][nt][3] + b2s[cl + 1], 0.f); s1 = fmaf(h, w3s[cl + 1], s1);
        }
        s0 += __shfl_xor_sync(0xffffffffu, s0, 1);
        s0 += __shfl_xor_sync(0xffffffffu, s0, 2);
        s1 += __shfl_xor_sync(0xffffffffu, s1, 1);
        s1 += __shfl_xor_sync(0xffffffffu, s1, 2);
        if (t4 == 0) {
            int p = wm * 64 + mt * 16 + g;
            sred[p * 5 + wn]       = s0;
            sred[(p + 8) * 5 + wn] = s1;
        }
    }
    __syncthreads();

    if (tid < 128) {
        float sum = sred[tid * 5] + sred[tid * 5 + 1] +
                    sred[tid * 5 + 2] + sred[tid * 5 + 3] + cd_b3[0];
        int i = i0 + (tid >> 3);
        int j = j0 + (tid & 7);
        float* cm = out + OFF_COL + b * (NOBJ * NOBJ);
        if (i < j) {
            float prob = 1.f / (1.f + expf(-sum));
            cm[i * NOBJ + j] = prob;
            cm[j * NOBJ + i] = prob;
        } else if (i == j) {
            cm[i * NOBJ + i] = 0.f;   // d_out poisoned; diagonal must be 0
        }
    }
}

// ---------------------------------------------------------------------------
extern "C" void kernel_launch(void* const* d_in, const int* in_sizes, int n_in,
                              void* d_out, int out_size)
{
    (void)in_sizes; (void)n_in; (void)out_size;
    const float* x     = (const float*)d_in[0];
    const float* pp_w1 = (const float*)d_in[1];
    const float* pp_b1 = (const float*)d_in[2];
    const float* pp_w2 = (const float*)d_in[3];
    const float* pp_b2 = (const float*)d_in[4];
    const float* cd_w1 = (const float*)d_in[5];
    const float* cd_b1 = (const float*)d_in[6];
    const float* cd_w2 = (const float*)d_in[7];
    const float* cd_b2 = (const float*)d_in[8];
    const float* cd_w3 = (const float*)d_in[9];
    const float* cd_b3 = (const float*)d_in[10];
    const float* vel_w = (const float*)d_in[11];
    const float* vel_b = (const float*)d_in[12];
    const float* frc_w = (const float*)d_in[13];
    const float* frc_b = (const float*)d_in[14];
    float* out = (float*)d_out;

    cudaFuncSetAttribute(pair_kernel, cudaFuncAttributeMaxDynamicSharedMemorySize, PAIR_SMEM);

    prep_w2t<<<32, 256>>>(cd_w2);        // 32*256 = 8192 = full table, exact
    heads_gemm<<<dim3(4, 16, 2), 256>>>(x, pp_w1, pp_b1, cd_w1, cd_b1);
    small_heads<<<128, 256>>>(x, pp_w2, pp_b2, vel_w, vel_b, frc_w, frc_b, out);
    pair_kernel<<<4 * 272, 256, PAIR_SMEM>>>(cd_b2, cd_w3, cd_b3, out);
}